// round 6
// baseline (speedup 1.0000x reference)
#include <cuda_runtime.h>
#include <cuda_fp16.h>
#include <cstdint>

#define BATCH 32
#define HH 512
#define WW 512
#define NPX (BATCH * HH * WW)

#define TX 64  // output tile width
#define TY 64  // output tile height
#define SW 72  // smem tile width  (TX + 8)
#define SH 72  // smem tile height (TY + 8)
#define NGRP (SH * (SW / 4))  // 1296 4-px fill groups

// 9x9 kernel weights in constant bank
__constant__ float c_w[81];

// Scratch (device globals: allocation-free per harness rules)
__device__ __half g_lm[NPX];   // local mean, fp16
__device__ __half g_s2[NPX];   // channel-mean squared-dev, fp16
__device__ __half g_sig[NPX];  // sigma, fp16
__device__ float  g_part[BATCH * 64];

typedef unsigned long long u64;

// --- f32x2 packed-math helpers (Blackwell FFMA2 path) ----------------------
__device__ __forceinline__ u64 bcast2(float w) {
    u64 r;
    asm("mov.b64 %0, {%1, %1};" : "=l"(r) : "r"(__float_as_uint(w)));
    return r;
}
__device__ __forceinline__ void fma2(u64& acc, u64 a, u64 b) {
    asm("fma.rn.f32x2 %0, %1, %2, %0;" : "+l"(acc) : "l"(a), "l"(b));
}

// ---------------------------------------------------------------------------
// Blur core: block (32,8). Thread = 2 adjacent cols x 8 rows. Even taps read
// the aligned tile, odd taps the 1-element-shifted copy -> aligned 8B loads.
// Loads are plain C u64 derefs: ptxas folds j*288 into LDS.64 [R+imm]
// (no per-load IADD) and schedules batches itself. Weights hoisted per
// tap-column (81 LDC total/thread).
// ---------------------------------------------------------------------------
__device__ __forceinline__ void blur64(const float* sm, const float* smS,
                                       int tx, int tz, u64 acc[8]) {
#pragma unroll
    for (int i = 0; i < 8; i++) acc[i] = 0ull;

#pragma unroll 1
    for (int k = 0; k < 9; k += 2) {  // even taps
        u64 w2[9];
#pragma unroll
        for (int ky = 0; ky < 9; ky++) w2[ky] = bcast2(c_w[ky * 9 + k]);
        const u64* base = (const u64*)(sm + (8 * tz) * SW + 2 * tx + k);
        u64 v[16];
#pragma unroll
        for (int j = 0; j < 16; j++) v[j] = base[j * (SW / 2)];
#pragma unroll
        for (int j = 0; j < 16; j++) {
#pragma unroll
            for (int oy = 0; oy < 8; oy++) {
                int ky = j - oy;
                if (ky >= 0 && ky < 9) fma2(acc[oy], w2[ky], v[j]);
            }
        }
    }
#pragma unroll 1
    for (int k = 1; k < 9; k += 2) {  // odd taps via shifted copy
        u64 w2[9];
#pragma unroll
        for (int ky = 0; ky < 9; ky++) w2[ky] = bcast2(c_w[ky * 9 + k]);
        const u64* base = (const u64*)(smS + (8 * tz) * SW + 2 * tx + (k - 1));
        u64 v[16];
#pragma unroll
        for (int j = 0; j < 16; j++) v[j] = base[j * (SW / 2)];
#pragma unroll
        for (int j = 0; j < 16; j++) {
#pragma unroll
            for (int oy = 0; oy < 8; oy++) {
                int ky = j - oy;
                if (ky >= 0 && ky < 9) fma2(acc[oy], w2[ky], v[j]);
            }
        }
    }
}

// ---------------------------------------------------------------------------
// Stage 1: vectorized fill (4 px/group: 3x LDG.128 -> m,q), build m (f32,
// aligned + shifted) and q (fp16) tiles; blur m -> lm; s2 = q - 2*lm*m + lm^2.
// Groups are 4-px aligned and H/W are multiples of 4 -> a group is entirely
// in-range or entirely out (zero pad), no straddling.
// ---------------------------------------------------------------------------
__global__ __launch_bounds__(256, 4) void k_stage1(const float* __restrict__ x) {
    extern __shared__ float dsm[];
    float*  sm  = dsm;                           // [SH][SW] f32
    float*  smS = dsm + SH * SW;                 // shifted copy f32
    __half* sq  = (__half*)(dsm + 2 * SH * SW);  // [SH][SW] fp16

    const int b = blockIdx.z;
    const int x0 = blockIdx.x * TX, y0 = blockIdx.y * TY;
    const int tid = threadIdx.y * 32 + threadIdx.x;
    const float inv3 = 1.f / 3.f;

    {
        int r = tid / 18, c = tid - r * 18;
        for (int g = tid; g < NGRP; g += 256) {
            int gy = y0 - 4 + r, gx = x0 - 4 + 4 * c;
            float m0 = 0, m1 = 0, m2 = 0, m3 = 0;
            float q0 = 0, q1 = 0, q2 = 0, q3 = 0;
            if ((unsigned)gy < (unsigned)HH && (unsigned)gx < (unsigned)WW) {
                const float4* p =
                    (const float4*)(x + ((size_t)(b * HH + gy) * WW + gx) * 3);
                float4 A = __ldcs(p), B = __ldcs(p + 1), C = __ldcs(p + 2);
                m0 = (A.x + A.y + A.z) * inv3;
                m1 = (A.w + B.x + B.y) * inv3;
                m2 = (B.z + B.w + C.x) * inv3;
                m3 = (C.y + C.z + C.w) * inv3;
                q0 = fmaf(A.x, A.x, fmaf(A.y, A.y, A.z * A.z)) * inv3;
                q1 = fmaf(A.w, A.w, fmaf(B.x, B.x, B.y * B.y)) * inv3;
                q2 = fmaf(B.z, B.z, fmaf(B.w, B.w, C.x * C.x)) * inv3;
                q3 = fmaf(C.y, C.y, fmaf(C.z, C.z, C.w * C.w)) * inv3;
            }
            int i = r * SW + 4 * c;
            *(float4*)&sm[i] = make_float4(m0, m1, m2, m3);
            *(__half2*)&sq[i] = __floats2half2_rn(q0, q1);
            *(__half2*)&sq[i + 2] = __floats2half2_rn(q2, q3);
            if (c) smS[i - 1] = m0;
            smS[i] = m1;
            smS[i + 1] = m2;
            smS[i + 2] = m3;
            // advance (r,c) by 256 groups = 14*18 + 4
            c += 4;
            r += 14;
            if (c >= 18) { c -= 18; r += 1; }
        }
    }
    __syncthreads();

    const int tx = threadIdx.x, tz = threadIdx.y;
    u64 acc[8];
    blur64(sm, smS, tx, tz, acc);

#pragma unroll
    for (int oy = 0; oy < 8; oy++) {
        float lm0 = __uint_as_float((uint32_t)acc[oy]);
        float lm1 = __uint_as_float((uint32_t)(acc[oy] >> 32));
        int si = (8 * tz + oy + 4) * SW + 2 * tx + 4;
        float2 mm = *(const float2*)&sm[si];
        float2 qq = __half22float2(*(const __half2*)&sq[si]);
        float s20 = fmaxf(fmaf(lm0, fmaf(-2.f, mm.x, lm0), qq.x), 0.f);
        float s21 = fmaxf(fmaf(lm1, fmaf(-2.f, mm.y, lm1), qq.y), 0.f);
        int idx = (b * HH + y0 + 8 * tz + oy) * WW + x0 + 2 * tx;
        __stcs((__half2*)&g_lm[idx], __floats2half2_rn(lm0, lm1));
        __stcs((__half2*)&g_s2[idx], __floats2half2_rn(s20, s21));
    }
}

// ---------------------------------------------------------------------------
// Stage 2: vectorized fill (4 px/group via LDG.64 of 4 halves), blur s2 ->
// sigma = sqrt(.), write sigma fp16 + per-block partials. 5 CTAs/SM.
// ---------------------------------------------------------------------------
__global__ __launch_bounds__(256, 5) void k_stage2() {
    __shared__ __align__(16) float ss[SH * SW];
    __shared__ __align__(16) float ssS[SH * SW];
    __shared__ float warpsum[8];

    const int b = blockIdx.z;
    const int x0 = blockIdx.x * TX, y0 = blockIdx.y * TY;
    const int tid = threadIdx.y * 32 + threadIdx.x;

    {
        int r = tid / 18, c = tid - r * 18;
        for (int g = tid; g < NGRP; g += 256) {
            int gy = y0 - 4 + r, gx = x0 - 4 + 4 * c;
            float f0 = 0, f1 = 0, f2 = 0, f3 = 0;
            if ((unsigned)gy < (unsigned)HH && (unsigned)gx < (unsigned)WW) {
                uint2 u = __ldcs((const uint2*)&g_s2[(b * HH + gy) * WW + gx]);
                float2 a = __half22float2(*(__half2*)&u.x);
                float2 d = __half22float2(*(__half2*)&u.y);
                f0 = a.x; f1 = a.y; f2 = d.x; f3 = d.y;
            }
            int i = r * SW + 4 * c;
            *(float4*)&ss[i] = make_float4(f0, f1, f2, f3);
            if (c) ssS[i - 1] = f0;
            ssS[i] = f1;
            ssS[i + 1] = f2;
            ssS[i + 2] = f3;
            c += 4;
            r += 14;
            if (c >= 18) { c -= 18; r += 1; }
        }
    }
    __syncthreads();

    const int tx = threadIdx.x, tz = threadIdx.y;
    u64 acc[8];
    blur64(ss, ssS, tx, tz, acc);

    float lsum = 0.f;
#pragma unroll
    for (int oy = 0; oy < 8; oy++) {
        float s0 = sqrtf(fmaxf(__uint_as_float((uint32_t)acc[oy]), 0.f));
        float s1 = sqrtf(fmaxf(__uint_as_float((uint32_t)(acc[oy] >> 32)), 0.f));
        int idx = (b * HH + y0 + 8 * tz + oy) * WW + x0 + 2 * tx;
        __stcs((__half2*)&g_sig[idx], __floats2half2_rn(s0, s1));
        lsum += s0 + s1;
    }

#pragma unroll
    for (int o = 16; o > 0; o >>= 1)
        lsum += __shfl_down_sync(0xFFFFFFFFu, lsum, o);
    if (tx == 0) warpsum[tz] = lsum;
    __syncthreads();
    if (tid == 0) {
        float t = 0.f;
#pragma unroll
        for (int i = 0; i < 8; i++) t += warpsum[i];
        g_part[b * 64 + blockIdx.y * 8 + blockIdx.x] = t;
    }
}

// ---------------------------------------------------------------------------
// Final: prologue re-reduces this batch's 64 partials (L2 hits) -> ms, then
// out = (x - lm) / max(ms, sigma). 8 px / thread, streaming float4 traffic.
// ---------------------------------------------------------------------------
__global__ __launch_bounds__(256) void k_final(const float* __restrict__ x,
                                               float* __restrict__ out) {
    __shared__ float s_w[2];
    __shared__ float s_ms;

    const int b = blockIdx.x >> 7;  // 128 blocks / batch
    if (threadIdx.x < 64) {
        float v = g_part[b * 64 + threadIdx.x];
#pragma unroll
        for (int o = 16; o > 0; o >>= 1)
            v += __shfl_down_sync(0xFFFFFFFFu, v, o);
        if ((threadIdx.x & 31) == 0) s_w[threadIdx.x >> 5] = v;
    }
    __syncthreads();
    if (threadIdx.x == 0)
        s_ms = (s_w[0] + s_w[1]) * (1.f / ((float)HH * (float)WW));
    __syncthreads();
    const float ms = s_ms;

    const int p = (blockIdx.x & 127) * 2048 + threadIdx.x * 8 + (b << 18);

    uint4 lmu = __ldcs((const uint4*)((const __half*)g_lm + p));
    uint4 sgu = __ldcs((const uint4*)((const __half*)g_sig + p));
    const __half2* lmh = (const __half2*)&lmu;
    const __half2* sgh = (const __half2*)&sgu;

    const float4* xp = (const float4*)(x + (size_t)p * 3);
    float4 xv[6];
#pragma unroll
    for (int i = 0; i < 6; i++) xv[i] = __ldcs(xp + i);

    float lmv[8], inv[8];
#pragma unroll
    for (int i = 0; i < 4; i++) {
        float2 l = __half22float2(lmh[i]);
        float2 s = __half22float2(sgh[i]);
        lmv[2 * i] = l.x;
        lmv[2 * i + 1] = l.y;
        inv[2 * i] = __frcp_rn(fmaxf(ms, s.x));
        inv[2 * i + 1] = __frcp_rn(fmaxf(ms, s.y));
    }

    const float* f = (const float*)xv;
    float4* op = (float4*)(out + (size_t)p * 3);
#pragma unroll
    for (int i = 0; i < 6; i++) {
        float o0 = (f[4 * i + 0] - lmv[(4 * i + 0) / 3]) * inv[(4 * i + 0) / 3];
        float o1 = (f[4 * i + 1] - lmv[(4 * i + 1) / 3]) * inv[(4 * i + 1) / 3];
        float o2 = (f[4 * i + 2] - lmv[(4 * i + 2) / 3]) * inv[(4 * i + 2) / 3];
        float o3 = (f[4 * i + 3] - lmv[(4 * i + 3) / 3]) * inv[(4 * i + 3) / 3];
        __stcs(op + i, make_float4(o0, o1, o2, o3));
    }
}

// ---------------------------------------------------------------------------
extern "C" void kernel_launch(void* const* d_in, const int* in_sizes, int n_in,
                              void* d_out, int out_size) {
    const float* x = (const float*)d_in[0];

    cudaMemcpyToSymbolAsync(c_w, d_in[1], 81 * sizeof(float), 0,
                            cudaMemcpyDeviceToDevice, 0);

    const int smem1 = (2 * SH * SW) * (int)sizeof(float) +
                      SH * SW * (int)sizeof(__half);  // 51840 B
    cudaFuncSetAttribute(k_stage1, cudaFuncAttributeMaxDynamicSharedMemorySize,
                         smem1);

    dim3 blk(32, 8);
    dim3 grd(WW / TX, HH / TY, BATCH);
    k_stage1<<<grd, blk, smem1>>>(x);
    k_stage2<<<grd, blk>>>();
    k_final<<<BATCH * 128, 256>>>(x, (float*)d_out);
}

// round 7
// speedup vs baseline: 1.0498x; 1.0498x over previous
#include <cuda_runtime.h>
#include <cuda_fp16.h>
#include <cstdint>

#define BATCH 32
#define HH 512
#define WW 512
#define NPX (BATCH * HH * WW)

#define TX 64  // output tile width
#define TY 64  // output tile height
#define SW 72  // smem tile width  (TX + 8)
#define SH 72  // smem tile height (TY + 8)
#define NGRP (SH * (SW / 4))  // 1296 4-px fill groups

// 9x9 kernel weights in constant bank
__constant__ float c_w[81];

// Scratch (device globals: allocation-free per harness rules)
__device__ __half g_lm[NPX];   // local mean, fp16
__device__ __half g_s2[NPX];   // channel-mean squared-dev, fp16
__device__ __half g_sig[NPX];  // sigma, fp16
__device__ float  g_part[BATCH * 64];

typedef unsigned long long u64;

// --- f32x2 packed-math helpers (Blackwell FFMA2 path) ----------------------
__device__ __forceinline__ u64 bcast2(float w) {
    u64 r;
    asm("mov.b64 %0, {%1, %1};" : "=l"(r) : "r"(__float_as_uint(w)));
    return r;
}
__device__ __forceinline__ void fma2(u64& acc, u64 a, u64 b) {
    asm("fma.rn.f32x2 %0, %1, %2, %0;" : "+l"(acc) : "l"(a), "l"(b));
}
// {lo = hi32(a), hi = w} : shifts an aligned pair one column right
__device__ __forceinline__ u64 pair_shift(u64 a, float w) {
    u64 r;
    asm("mov.b64 %0, {%1, %2};"
        : "=l"(r) : "r"((uint32_t)(a >> 32)), "r"(__float_as_uint(w)));
    return r;
}

// ---------------------------------------------------------------------------
// Blur core (in-place pair shift): block (32,8). Thread = 2 adjacent cols x
// 8 out rows (16-row input window). Per tap-pair p:
//   even tap 2p  : aligned LDS.64 pairs (cur)
//   shift        : LDS.32 of word 2p+2 -> cur becomes the odd-tap pair
//   odd tap 2p+1 : shifted cur
//   reload       : aligned LDS.64 at col p+1 (next even pair)
// Weights ky-outer: ONE broadcast pair live at a time -> fits 64 regs with
// cur[16] (32 regs) + acc[8] (16 regs). No shifted smem copy needed.
// ---------------------------------------------------------------------------
__device__ __forceinline__ void blur64(const float* sm, int tx, int tz,
                                       u64 acc[8]) {
#pragma unroll
    for (int i = 0; i < 8; i++) acc[i] = 0ull;

    const u64*   b64 = (const u64*)sm + 4 * tz * SW + tx;  // (8tz*SW + 2tx)/2
    const float* b32 = sm + (8 * tz) * SW + 2 * tx;

    u64 cur[16];
#pragma unroll
    for (int j = 0; j < 16; j++) cur[j] = b64[j * (SW / 2)];

#pragma unroll
    for (int p = 0; p < 4; p++) {
        // even tap k = 2p
#pragma unroll
        for (int ky = 0; ky < 9; ky++) {
            u64 we = bcast2(c_w[ky * 9 + 2 * p]);
#pragma unroll
            for (int oy = 0; oy < 8; oy++) fma2(acc[oy], we, cur[ky + oy]);
        }
        // shift pairs one column right (word 2p+2)
#pragma unroll
        for (int j = 0; j < 16; j++)
            cur[j] = pair_shift(cur[j], b32[j * SW + 2 * p + 2]);
        // odd tap k = 2p+1
#pragma unroll
        for (int ky = 0; ky < 9; ky++) {
            u64 wo = bcast2(c_w[ky * 9 + 2 * p + 1]);
#pragma unroll
            for (int oy = 0; oy < 8; oy++) fma2(acc[oy], wo, cur[ky + oy]);
        }
        // reload next even pair (words 2p+2, 2p+3)
#pragma unroll
        for (int j = 0; j < 16; j++) cur[j] = b64[j * (SW / 2) + p + 1];
    }
    // tail tap k = 8
#pragma unroll
    for (int ky = 0; ky < 9; ky++) {
        u64 we = bcast2(c_w[ky * 9 + 8]);
#pragma unroll
        for (int oy = 0; oy < 8; oy++) fma2(acc[oy], we, cur[ky + oy]);
    }
}

// ---------------------------------------------------------------------------
// Stage 1: vectorized fill (4 px/group: 3x LDG.128 -> m f32 + q fp16 tiles),
// blur m -> lm, s2 = q - 2*lm*m + lm^2. smem = 31.1 KB (no shifted copy).
// ---------------------------------------------------------------------------
__global__ __launch_bounds__(256, 4) void k_stage1(const float* __restrict__ x) {
    extern __shared__ float dsm[];
    float*  sm = dsm;                          // [SH][SW] f32
    __half* sq = (__half*)(dsm + SH * SW);     // [SH][SW] fp16

    const int b = blockIdx.z;
    const int x0 = blockIdx.x * TX, y0 = blockIdx.y * TY;
    const int tid = threadIdx.y * 32 + threadIdx.x;
    const float inv3 = 1.f / 3.f;

    {
        int r = tid / 18, c = tid - r * 18;
        for (int g = tid; g < NGRP; g += 256) {
            int gy = y0 - 4 + r, gx = x0 - 4 + 4 * c;
            float m0 = 0, m1 = 0, m2 = 0, m3 = 0;
            float q0 = 0, q1 = 0, q2 = 0, q3 = 0;
            if ((unsigned)gy < (unsigned)HH && (unsigned)gx < (unsigned)WW) {
                const float4* p =
                    (const float4*)(x + ((size_t)(b * HH + gy) * WW + gx) * 3);
                float4 A = __ldcs(p), B = __ldcs(p + 1), C = __ldcs(p + 2);
                m0 = (A.x + A.y + A.z) * inv3;
                m1 = (A.w + B.x + B.y) * inv3;
                m2 = (B.z + B.w + C.x) * inv3;
                m3 = (C.y + C.z + C.w) * inv3;
                q0 = fmaf(A.x, A.x, fmaf(A.y, A.y, A.z * A.z)) * inv3;
                q1 = fmaf(A.w, A.w, fmaf(B.x, B.x, B.y * B.y)) * inv3;
                q2 = fmaf(B.z, B.z, fmaf(B.w, B.w, C.x * C.x)) * inv3;
                q3 = fmaf(C.y, C.y, fmaf(C.z, C.z, C.w * C.w)) * inv3;
            }
            int i = r * SW + 4 * c;
            *(float4*)&sm[i] = make_float4(m0, m1, m2, m3);
            __half2 qa = __floats2half2_rn(q0, q1);
            __half2 qb = __floats2half2_rn(q2, q3);
            *(uint2*)&sq[i] =
                make_uint2(*(uint32_t*)&qa, *(uint32_t*)&qb);
            c += 4;
            r += 14;
            if (c >= 18) { c -= 18; r += 1; }
        }
    }
    __syncthreads();

    const int tx = threadIdx.x, tz = threadIdx.y;
    u64 acc[8];
    blur64(sm, tx, tz, acc);

#pragma unroll
    for (int oy = 0; oy < 8; oy++) {
        float lm0 = __uint_as_float((uint32_t)acc[oy]);
        float lm1 = __uint_as_float((uint32_t)(acc[oy] >> 32));
        int si = (8 * tz + oy + 4) * SW + 2 * tx + 4;
        float2 mm = *(const float2*)&sm[si];
        float2 qq = __half22float2(*(const __half2*)&sq[si]);
        float s20 = fmaxf(fmaf(lm0, fmaf(-2.f, mm.x, lm0), qq.x), 0.f);
        float s21 = fmaxf(fmaf(lm1, fmaf(-2.f, mm.y, lm1), qq.y), 0.f);
        int idx = (b * HH + y0 + 8 * tz + oy) * WW + x0 + 2 * tx;
        __stcs((__half2*)&g_lm[idx], __floats2half2_rn(lm0, lm1));
        __stcs((__half2*)&g_s2[idx], __floats2half2_rn(s20, s21));
    }
}

// ---------------------------------------------------------------------------
// Stage 2: fill ss (f32) from fp16 s2, blur -> sigma = sqrt(.), write sigma
// fp16 + per-block partials. smem = 20.8 KB.
// ---------------------------------------------------------------------------
__global__ __launch_bounds__(256, 4) void k_stage2() {
    __shared__ __align__(16) float ss[SH * SW];
    __shared__ float warpsum[8];

    const int b = blockIdx.z;
    const int x0 = blockIdx.x * TX, y0 = blockIdx.y * TY;
    const int tid = threadIdx.y * 32 + threadIdx.x;

    {
        int r = tid / 18, c = tid - r * 18;
        for (int g = tid; g < NGRP; g += 256) {
            int gy = y0 - 4 + r, gx = x0 - 4 + 4 * c;
            float f0 = 0, f1 = 0, f2 = 0, f3 = 0;
            if ((unsigned)gy < (unsigned)HH && (unsigned)gx < (unsigned)WW) {
                uint2 u = __ldcs((const uint2*)&g_s2[(b * HH + gy) * WW + gx]);
                float2 a = __half22float2(*(__half2*)&u.x);
                float2 d = __half22float2(*(__half2*)&u.y);
                f0 = a.x; f1 = a.y; f2 = d.x; f3 = d.y;
            }
            int i = r * SW + 4 * c;
            *(float4*)&ss[i] = make_float4(f0, f1, f2, f3);
            c += 4;
            r += 14;
            if (c >= 18) { c -= 18; r += 1; }
        }
    }
    __syncthreads();

    const int tx = threadIdx.x, tz = threadIdx.y;
    u64 acc[8];
    blur64(ss, tx, tz, acc);

    float lsum = 0.f;
#pragma unroll
    for (int oy = 0; oy < 8; oy++) {
        float s0 = sqrtf(fmaxf(__uint_as_float((uint32_t)acc[oy]), 0.f));
        float s1 = sqrtf(fmaxf(__uint_as_float((uint32_t)(acc[oy] >> 32)), 0.f));
        int idx = (b * HH + y0 + 8 * tz + oy) * WW + x0 + 2 * tx;
        __stcs((__half2*)&g_sig[idx], __floats2half2_rn(s0, s1));
        lsum += s0 + s1;
    }

#pragma unroll
    for (int o = 16; o > 0; o >>= 1)
        lsum += __shfl_down_sync(0xFFFFFFFFu, lsum, o);
    if (tx == 0) warpsum[tz] = lsum;
    __syncthreads();
    if (tid == 0) {
        float t = 0.f;
#pragma unroll
        for (int i = 0; i < 8; i++) t += warpsum[i];
        g_part[b * 64 + blockIdx.y * 8 + blockIdx.x] = t;
    }
}

// ---------------------------------------------------------------------------
// Final: prologue re-reduces this batch's 64 partials (L2 hits) -> ms, then
// out = (x - lm) / max(ms, sigma). 8 px / thread, streaming float4 traffic.
// ---------------------------------------------------------------------------
__global__ __launch_bounds__(256) void k_final(const float* __restrict__ x,
                                               float* __restrict__ out) {
    __shared__ float s_w[2];
    __shared__ float s_ms;

    const int b = blockIdx.x >> 7;  // 128 blocks / batch
    if (threadIdx.x < 64) {
        float v = g_part[b * 64 + threadIdx.x];
#pragma unroll
        for (int o = 16; o > 0; o >>= 1)
            v += __shfl_down_sync(0xFFFFFFFFu, v, o);
        if ((threadIdx.x & 31) == 0) s_w[threadIdx.x >> 5] = v;
    }
    __syncthreads();
    if (threadIdx.x == 0)
        s_ms = (s_w[0] + s_w[1]) * (1.f / ((float)HH * (float)WW));
    __syncthreads();
    const float ms = s_ms;

    const int p = (blockIdx.x & 127) * 2048 + threadIdx.x * 8 + (b << 18);

    uint4 lmu = __ldcs((const uint4*)((const __half*)g_lm + p));
    uint4 sgu = __ldcs((const uint4*)((const __half*)g_sig + p));
    const __half2* lmh = (const __half2*)&lmu;
    const __half2* sgh = (const __half2*)&sgu;

    const float4* xp = (const float4*)(x + (size_t)p * 3);
    float4 xv[6];
#pragma unroll
    for (int i = 0; i < 6; i++) xv[i] = __ldcs(xp + i);

    float lmv[8], inv[8];
#pragma unroll
    for (int i = 0; i < 4; i++) {
        float2 l = __half22float2(lmh[i]);
        float2 s = __half22float2(sgh[i]);
        lmv[2 * i] = l.x;
        lmv[2 * i + 1] = l.y;
        inv[2 * i] = __frcp_rn(fmaxf(ms, s.x));
        inv[2 * i + 1] = __frcp_rn(fmaxf(ms, s.y));
    }

    const float* f = (const float*)xv;
    float4* op = (float4*)(out + (size_t)p * 3);
#pragma unroll
    for (int i = 0; i < 6; i++) {
        float o0 = (f[4 * i + 0] - lmv[(4 * i + 0) / 3]) * inv[(4 * i + 0) / 3];
        float o1 = (f[4 * i + 1] - lmv[(4 * i + 1) / 3]) * inv[(4 * i + 1) / 3];
        float o2 = (f[4 * i + 2] - lmv[(4 * i + 2) / 3]) * inv[(4 * i + 2) / 3];
        float o3 = (f[4 * i + 3] - lmv[(4 * i + 3) / 3]) * inv[(4 * i + 3) / 3];
        __stcs(op + i, make_float4(o0, o1, o2, o3));
    }
}

// ---------------------------------------------------------------------------
extern "C" void kernel_launch(void* const* d_in, const int* in_sizes, int n_in,
                              void* d_out, int out_size) {
    const float* x = (const float*)d_in[0];

    cudaMemcpyToSymbolAsync(c_w, d_in[1], 81 * sizeof(float), 0,
                            cudaMemcpyDeviceToDevice, 0);

    const int smem1 = SH * SW * (int)sizeof(float) +
                      SH * SW * (int)sizeof(__half);  // 31104 B
    cudaFuncSetAttribute(k_stage1, cudaFuncAttributeMaxDynamicSharedMemorySize,
                         smem1);

    dim3 blk(32, 8);
    dim3 grd(WW / TX, HH / TY, BATCH);
    k_stage1<<<grd, blk, smem1>>>(x);
    k_stage2<<<grd, blk>>>();
    k_final<<<BATCH * 128, 256>>>(x, (float*)d_out);
}